// round 14
// baseline (speedup 1.0000x reference)
#include <cuda_runtime.h>
#include <cuda_bf16.h>
#include <cuda_fp16.h>

#define NTH 128
#define SEQ 101
#define HPAD 20   // padded row stride for D=16 activations
#define QPAD 112  // padded q slots per head (16 thr x 7 q)
#define KP   51   // key pairs (101 keys + 1 zero pad)

// q pre-scale: (1/sqrt(head_dim=2)) * log2(e), so exp(score) == exp2(q'.k)
#define QSC (0.7071067811865476f * 1.4426950408889634f)

typedef unsigned long long ull;
struct ull2 { ull x, y; };

__device__ __forceinline__ ull pack2(float a, float b) {
    ull r; asm("mov.b64 %0, {%1, %2};" : "=l"(r) : "f"(a), "f"(b)); return r;
}
__device__ __forceinline__ void unpack2(ull p, float& a, float& b) {
    asm("mov.b64 {%0, %1}, %2;" : "=f"(a), "=f"(b) : "l"(p));
}
__device__ __forceinline__ ull fma2u(ull a, ull b, ull c) {
    ull d; asm("fma.rn.f32x2 %0, %1, %2, %3;" : "=l"(d) : "l"(a), "l"(b), "l"(c)); return d;
}
__device__ __forceinline__ ull mul2u(ull a, ull b) {
    ull d; asm("mul.rn.f32x2 %0, %1, %2;" : "=l"(d) : "l"(a), "l"(b)); return d;
}
__device__ __forceinline__ ull add2u(ull a, ull b) {
    ull d; asm("add.rn.f32x2 %0, %1, %2;" : "=l"(d) : "l"(a), "l"(b)); return d;
}

// Two exp2 in ONE MUFU op: f32 pair -> f16x2 -> ex2.approx.f16x2 -> f32 pair.
// Scores are |sc| <~ 2 (0.1-scaled weights on LN'd activations), so the fp16
// rounding of sc costs ~7e-4 relative on each exp; softmax normalization
// cancels the common mode. Pad scores are exactly 0 -> exp2 = 1 exactly.
__device__ __forceinline__ ull exp2_pair(float sa, float sb) {
    unsigned int h2, eh;
    asm("cvt.rn.f16x2.f32 %0, %1, %2;" : "=r"(h2) : "f"(sb), "f"(sa)); // lo=sa, hi=sb
    asm("ex2.approx.f16x2 %0, %1;" : "=r"(eh) : "r"(h2));
    float e0, e1;
    asm("{\n\t.reg .b16 lo, hi;\n\t"
        "mov.b32 {lo, hi}, %2;\n\t"
        "cvt.f32.f16 %0, lo;\n\t"
        "cvt.f32.f16 %1, hi;\n\t}"
        : "=f"(e0), "=f"(e1) : "r"(eh));
    return pack2(e0, e1);
}

// shared-memory layout (floats), total 9348 f = 36.5 KB (5 CTAs/SM)
#define OFF_Q    0      // float2 [8][112] = 1792 f ; x-stage aliases front region
#define OFF_KK   1792   // float4 [8][51] {k0e,k0o,k1e,k1o} = 1632 f
#define OFF_VV   3424   // float4 [8][51] {v0e,v0o,v1e,v1o} = 1632 f
#define OFF_H    5056   // 101*20 = 2020 f
#define OFF_WQ   7076   // 768 f   (also head scratch after last layer)
#define OFF_WO   7844
#define OFF_W1   8100
#define OFF_W2   8356
#define OFF_CW   8612   // 560 f
#define OFF_BQ   9172   // 48 f
#define OFF_BO   9220
#define OFF_B1   9236
#define OFF_B2   9252
#define OFF_G1   9268
#define OFF_BE1  9284
#define OFF_G2   9300
#define OFF_BE2  9316
#define OFF_CB   9332
#define SM_TOT   9348

// QKV for one token: 48 outputs from hr[16] (registers) + broadcast weights.
// Writes pre-scaled q to s_q[h][s] and scatters k/v into key-pair layout.
__device__ __forceinline__ void qkv_token(const float* __restrict__ sm,
                                          float2* s_q, float* s_kk, float* s_vv,
                                          const float hr[16], int s)
{
    const int pr = (s >> 1) * 4 + (s & 1);   // pair-slot base for this token
    #pragma unroll
    for (int h = 0; h < 8; h++) {
        float acc[6];
        #pragma unroll
        for (int r = 0; r < 6; r++) {
            const int e = (r >> 1) * 16 + 2 * h + (r & 1);
            const float4* w4 = (const float4*)(sm + OFF_WQ + e * 16);
            float a = sm[OFF_BQ + e];
            #pragma unroll
            for (int j = 0; j < 4; j++) {
                const float4 wv = w4[j];
                a = fmaf(hr[4*j],   wv.x, a);
                a = fmaf(hr[4*j+1], wv.y, a);
                a = fmaf(hr[4*j+2], wv.z, a);
                a = fmaf(hr[4*j+3], wv.w, a);
            }
            acc[r] = a;
        }
        s_q[h * QPAD + s] = make_float2(acc[0] * QSC, acc[1] * QSC);
        float* kkh = s_kk + h * (KP * 4);
        float* vvh = s_vv + h * (KP * 4);
        kkh[pr]     = acc[2];   // k0
        kkh[pr + 2] = acc[3];   // k1
        vvh[pr]     = acc[4];   // v0
        vvh[pr + 2] = acc[5];   // v1
    }
}

__global__ __launch_bounds__(NTH, 5) void TorrinE0_kernel(
    const float* __restrict__ x,
    const float* __restrict__ conv_w,
    const float* __restrict__ conv_b,
    const float* __restrict__ cls_emb,
    const float* __restrict__ Wqkv,
    const float* __restrict__ bqkv,
    const float* __restrict__ Wo,
    const float* __restrict__ bo,
    const float* __restrict__ W1,
    const float* __restrict__ b1,
    const float* __restrict__ W2,
    const float* __restrict__ b2,
    const float* __restrict__ ln1g, const float* __restrict__ ln1b,
    const float* __restrict__ ln2g, const float* __restrict__ ln2b,
    const float* __restrict__ lnfg, const float* __restrict__ lnfb,
    const float* __restrict__ endw, const float* __restrict__ endb,
    const float* __restrict__ headw, const float* __restrict__ headb,
    float* __restrict__ out)
{
    __shared__ __align__(16) float sm[SM_TOT];
    float2* s_q  = (float2*)sm;             // [h][QPAD] ; ctx written back in-place
    float*  s_kk = sm + OFF_KK;             // [h][KP] float4-shaped
    float*  s_vv = sm + OFF_VV;
    float*  s_h  = sm + OFF_H;

    const int tid = threadIdx.x;
    const int b   = blockIdx.x;

    // ---- stage full x row into q/kk/vv union (dead until QKV[0]) + weights ----
    {
        const float4* xg = (const float4*)(x + (size_t)b * 3500);
        float4* xb = (float4*)sm;
        #pragma unroll 2
        for (int i = tid; i < 875; i += NTH) xb[i] = xg[i];
        for (int i = tid; i < 560; i += NTH) sm[OFF_CW + i] = conv_w[i];
        for (int i = tid; i < 768; i += NTH) sm[OFF_WQ + i] = Wqkv[i];   // layer 0
        if (tid < 48) sm[OFF_BQ + tid] = bqkv[tid];
        if (tid < 16) {
            s_h[tid]          = cls_emb[tid];   // cls token = row 0
            sm[OFF_CB + tid]  = conv_b[tid];
        }
    }
    __syncthreads();

    // ---- conv patchifier: 100 patches x 16 filters, K=35 (single pass) ----
    for (int idx = tid; idx < 1600; idx += NTH) {
        const int p = idx >> 4, f = idx & 15;
        const float* xp = sm + p * 35;
        const float* wf = sm + OFF_CW + f * 35;
        float acc = sm[OFF_CB + f];
        #pragma unroll
        for (int k = 0; k < 35; k++) acc = fmaf(xp[k], wf[k], acc);
        s_h[(p + 1) * HPAD + f] = acc;
    }
    __syncthreads();

    // ---- one-time pad zeroing (x now dead):
    //      q pad slots s=101..111 (stay zero: writes are always s<101),
    //      kk/vv odd halves of pair 50 ----
    for (int i = tid; i < 8 * (QPAD - SEQ); i += NTH) {
        const int h = i / (QPAD - SEQ);
        const int s = SEQ + i % (QPAD - SEQ);
        s_q[h * QPAD + s] = make_float2(0.f, 0.f);
    }
    if (tid < 32) {
        const int h = tid >> 2, w = tid & 3;   // 0=kk201,1=kk203,2=vv201,3=vv203
        float* base = (w < 2) ? s_kk : s_vv;
        base[h * (KP * 4) + 200 + 1 + 2 * (w & 1)] = 0.f;
    }
    __syncthreads();

    // ---- QKV for layer 0 (standalone; h comes from conv, not registers) ----
    if (tid < SEQ) {
        float hr[16];
        const float4* h4 = (const float4*)(s_h + tid * HPAD);
        #pragma unroll
        for (int j = 0; j < 4; j++) {
            const float4 v = h4[j];
            hr[4*j] = v.x; hr[4*j+1] = v.y; hr[4*j+2] = v.z; hr[4*j+3] = v.w;
        }
        qkv_token(sm, s_q, s_kk, s_vv, hr, tid);
    }
    __syncthreads();

    for (int l = 0; l < 8; l++) {
        // ---- stage layer-l weights + next layer's Wqkv (NO sync here: the
        //      post-attention sync covers visibility; attention reads none) ----
        for (int i = tid; i < 256; i += NTH) {
            sm[OFF_WO + i] = Wo[l * 256 + i];
            sm[OFF_W1 + i] = W1[l * 256 + i];
            sm[OFF_W2 + i] = W2[l * 256 + i];
        }
        if (l < 7) {
            for (int i = tid; i < 768; i += NTH) sm[OFF_WQ + i] = Wqkv[(l + 1) * 768 + i];
            if (tid < 48) sm[OFF_BQ + tid] = bqkv[(l + 1) * 48 + tid];
        }
        if (tid < 16) {
            sm[OFF_BO  + tid] = bo[l * 16 + tid];
            sm[OFF_B1  + tid] = b1[l * 16 + tid];
            sm[OFF_B2  + tid] = b2[l * 16 + tid];
            sm[OFF_G1  + tid] = ln1g[l * 16 + tid];
            sm[OFF_BE1 + tid] = ln1b[l * 16 + tid];
            sm[OFF_G2  + tid] = ln2g[l * 16 + tid];
            sm[OFF_BE2 + tid] = ln2b[l * 16 + tid];
        }

        // ---- attention: 16 threads/head x 7 queries; key-pair packed f32x2;
        //      ONE f16x2 MUFU ex2 per key pair (halves the MUFU floor) ----
        {
            const int h  = tid >> 4;          // 0..7
            const int j  = tid & 15;          // 0..15
            const int s0 = j * 7;             // <= 105; +6 = 111 < QPAD
            float2* qh = s_q + h * QPAD;

            ull q0b[7], q1b[7];
            #pragma unroll
            for (int q = 0; q < 7; q++) {
                const float2 qv = qh[s0 + q];
                q0b[q] = pack2(qv.x, qv.x);
                q1b[q] = pack2(qv.y, qv.y);
            }
            ull sum2[7], c0[7], c1[7];
            #pragma unroll
            for (int q = 0; q < 7; q++) {
                sum2[q] = pack2(0.f, 0.f);
                c0[q]   = pack2(0.f, 0.f);
                c1[q]   = pack2(0.f, 0.f);
            }
            const ull2* kkp = (const ull2*)(s_kk + h * (KP * 4));
            const ull2* vvp = (const ull2*)(s_vv + h * (KP * 4));
            #pragma unroll 3
            for (int p = 0; p < KP; p++) {
                const ull2 kk = kkp[p];   // {k0 pair, k1 pair}
                const ull2 vv = vvp[p];   // {v0 pair, v1 pair}
                #pragma unroll
                for (int q = 0; q < 7; q++) {
                    const ull sc2 = fma2u(q1b[q], kk.y, mul2u(q0b[q], kk.x));
                    float sa, sb;
                    unpack2(sc2, sa, sb);
                    const ull e01 = exp2_pair(sa, sb);
                    sum2[q] = add2u(sum2[q], e01);
                    c0[q]   = fma2u(e01, vv.x, c0[q]);
                    c1[q]   = fma2u(e01, vv.y, c1[q]);
                }
            }
            #pragma unroll
            for (int q = 0; q < 7; q++) {
                const int s = s0 + q;
                if (s < SEQ) {
                    float sl, sh_, a0, b0, a1, b1;
                    unpack2(sum2[q], sl, sh_);
                    unpack2(c0[q], a0, b0);
                    unpack2(c1[q], a1, b1);
                    const float sum = sl + sh_ - 1.0f;   // remove pad key's e=1
                    const float inv = __fdividef(1.f, sum);
                    qh[s] = make_float2((a0 + b0) * inv, (a1 + b1) * inv);
                }
            }
        }
        __syncthreads();   // attn results + staged weights visible

        // ---- fused per-token: attn_out + res + LN1 + FF + res + LN2, then
        //      QKV for layer l+1 directly from the LN2 registers ----
        if (tid < SEQ) {
            float cx[16];
            #pragma unroll
            for (int h = 0; h < 8; h++) {
                const float2 c = s_q[h * QPAD + tid];
                cx[2*h] = c.x; cx[2*h+1] = c.y;
            }
            float res[16];
            {
                const float4* r4 = (const float4*)(s_h + tid * HPAD);
                #pragma unroll
                for (int j = 0; j < 4; j++) {
                    const float4 v = r4[j];
                    res[4*j] = v.x; res[4*j+1] = v.y; res[4*j+2] = v.z; res[4*j+3] = v.w;
                }
            }
            float pre[16];
            float mu = 0.f;
            #pragma unroll
            for (int d = 0; d < 16; d++) {
                const float* wr = sm + OFF_WO + d * 16;   // broadcast reads
                float acc = sm[OFF_BO + d];
                #pragma unroll
                for (int e = 0; e < 16; e++) acc = fmaf(cx[e], wr[e], acc);
                acc += res[d];
                pre[d] = acc;
                mu += acc;
            }
            mu *= (1.f / 16.f);
            float var = 0.f;
            #pragma unroll
            for (int d = 0; d < 16; d++) { const float c = pre[d] - mu; var = fmaf(c, c, var); }
            float rs = rsqrtf(var * (1.f / 16.f) + 1e-5f);

            float hloc[16];
            #pragma unroll
            for (int d = 0; d < 16; d++)
                hloc[d] = (pre[d] - mu) * rs * sm[OFF_G1 + d] + sm[OFF_BE1 + d];

            float ff1[16];
            #pragma unroll
            for (int f = 0; f < 16; f++) {
                const float* wr = sm + OFF_W1 + f * 16;
                float acc = sm[OFF_B1 + f];
                #pragma unroll
                for (int d = 0; d < 16; d++) acc = fmaf(hloc[d], wr[d], acc);
                ff1[f] = fmaxf(acc, 0.f);
            }
            mu = 0.f;
            #pragma unroll
            for (int d = 0; d < 16; d++) {
                const float* wr = sm + OFF_W2 + d * 16;
                float acc = sm[OFF_B2 + d];
                #pragma unroll
                for (int f = 0; f < 16; f++) acc = fmaf(ff1[f], wr[f], acc);
                acc += hloc[d];
                pre[d] = acc;
                mu += acc;
            }
            mu *= (1.f / 16.f);
            var = 0.f;
            #pragma unroll
            for (int d = 0; d < 16; d++) { const float c = pre[d] - mu; var = fmaf(c, c, var); }
            rs = rsqrtf(var * (1.f / 16.f) + 1e-5f);

            float hn[16];   // LN2 output = next layer's hidden, kept in regs
            #pragma unroll
            for (int d = 0; d < 16; d++)
                hn[d] = (pre[d] - mu) * rs * sm[OFF_G2 + d] + sm[OFF_BE2 + d];

            // residual store for next layer
            {
                float4* o4 = (float4*)(s_h + tid * HPAD);
                #pragma unroll
                for (int j = 0; j < 4; j++)
                    o4[j] = make_float4(hn[4*j], hn[4*j+1], hn[4*j+2], hn[4*j+3]);
            }
            // QKV for next layer straight from registers (no reload, no extra sync)
            if (l < 7) qkv_token(sm, s_q, s_kk, s_vv, hn, tid);
        }
        __syncthreads();
    }

    // ---- final LN on cls token (row 0), then 16->100->1 head + sigmoid ----
    if (tid == 0) {
        float r[16];
        float mu = 0.f;
        #pragma unroll
        for (int d = 0; d < 16; d++) { r[d] = s_h[d]; mu += r[d]; }
        mu *= (1.f / 16.f);
        float var = 0.f;
        #pragma unroll
        for (int d = 0; d < 16; d++) { const float c = r[d] - mu; var = fmaf(c, c, var); }
        const float rs = rsqrtf(var * (1.f / 16.f) + 1e-5f);
        #pragma unroll
        for (int d = 0; d < 16; d++)
            sm[OFF_WQ + d] = (r[d] - mu) * rs * lnfg[d] + lnfb[d];
    }
    __syncthreads();
    if (tid < 100) {
        const float* wr = endw + tid * 16;
        float acc = endb[tid];
        #pragma unroll
        for (int d = 0; d < 16; d++) acc = fmaf(sm[OFF_WQ + d], wr[d], acc);
        sm[OFF_WQ + 64 + tid] = acc * headw[tid];   // fold head_w in
    }
    __syncthreads();
    if (tid == 0) {
        float z = headb[0];
        for (int i = 0; i < 100; i++) z += sm[OFF_WQ + 64 + i];
        out[b] = 1.f / (1.f + __expf(-z));
    }
}

extern "C" void kernel_launch(void* const* d_in, const int* in_sizes, int n_in,
                              void* d_out, int out_size) {
    const float* x      = (const float*)d_in[0];
    const float* conv_w = (const float*)d_in[1];
    const float* conv_b = (const float*)d_in[2];
    const float* cls    = (const float*)d_in[3];
    const float* Wqkv   = (const float*)d_in[4];
    const float* bqkv   = (const float*)d_in[5];
    const float* Wo     = (const float*)d_in[6];
    const float* bo     = (const float*)d_in[7];
    const float* W1     = (const float*)d_in[8];
    const float* b1     = (const float*)d_in[9];
    const float* W2     = (const float*)d_in[10];
    const float* b2     = (const float*)d_in[11];
    const float* ln1g   = (const float*)d_in[12];
    const float* ln1b   = (const float*)d_in[13];
    const float* ln2g   = (const float*)d_in[14];
    const float* ln2b   = (const float*)d_in[15];
    const float* lnfg   = (const float*)d_in[16];
    const float* lnfb   = (const float*)d_in[17];
    const float* endw   = (const float*)d_in[18];
    const float* endb   = (const float*)d_in[19];
    const float* headw  = (const float*)d_in[20];
    const float* headb  = (const float*)d_in[21];
    float* out = (float*)d_out;

    const int B = in_sizes[0] / 3500;   // 2048
    TorrinE0_kernel<<<B, NTH>>>(x, conv_w, conv_b, cls, Wqkv, bqkv, Wo, bo,
                                W1, b1, W2, b2, ln1g, ln1b, ln2g, ln2b,
                                lnfg, lnfb, endw, endb, headw, headb, out);
}

// round 15
// speedup vs baseline: 1.2897x; 1.2897x over previous
#include <cuda_runtime.h>
#include <cuda_bf16.h>
#include <cuda_fp16.h>

#define NTH 128
#define SEQ 101
#define HPAD 20   // padded row stride for D=16 activations
#define QPAD 112  // padded q slots per head (16 thr x 7 q)
#define KP   51   // key pairs (101 keys + 1 zero pad)

// q pre-scale: (1/sqrt(head_dim=2)) * log2(e), so exp(score) == exp2(q'.k)
#define QSC (0.7071067811865476f * 1.4426950408889634f)

typedef unsigned int uint;

// ---- fp16x2 helpers (all fixed-latency fma-pipe ops except ex2) ----
__device__ __forceinline__ uint hmul2u(uint a, uint b) {
    uint d; asm("mul.f16x2 %0, %1, %2;" : "=r"(d) : "r"(a), "r"(b)); return d;
}
__device__ __forceinline__ uint hfma2u(uint a, uint b, uint c) {
    uint d; asm("fma.rn.f16x2 %0, %1, %2, %3;" : "=r"(d) : "r"(a), "r"(b), "r"(c)); return d;
}
__device__ __forceinline__ uint hadd2u(uint a, uint b) {
    uint d; asm("add.f16x2 %0, %1, %2;" : "=r"(d) : "r"(a), "r"(b)); return d;
}
__device__ __forceinline__ uint ex2h2(uint x) {
    uint d; asm("ex2.approx.f16x2 %0, %1;" : "=r"(d) : "r"(x)); return d;
}
// pack {a,a} into h2 (one cvt op; used once per query per tile, NOT in the loop)
__device__ __forceinline__ uint bcast_h2(float a) {
    uint d; asm("cvt.rn.f16x2.f32 %0, %1, %1;" : "=r"(d) : "f"(a)); return d;
}
__device__ __forceinline__ void h2_to_f32(uint h, float& lo, float& hi) {
    asm("{\n\t.reg .b16 l, hh;\n\t"
        "mov.b32 {l, hh}, %2;\n\t"
        "cvt.f32.f16 %0, l;\n\t"
        "cvt.f32.f16 %1, hh;\n\t}"
        : "=f"(lo), "=f"(hi) : "r"(h));
}

// shared-memory layout (floats), total 7796 f = 30.5 KB
// front region [0..3504) = q + kk + vv + pad; x row (3500 f) staged there (dead until QKV[0])
#define OFF_Q    0      // float2 [8][112] = 1792 f
#define OFF_KK   1792   // h2 words [8][51][2] = 816 f  ({k0e,k0o},{k1e,k1o} per pair)
#define OFF_VV   2608   // h2 words [8][51][2] = 816 f
#define OFF_H    3504   // 101*20 = 2020 f  (starts past x's 3500)
#define OFF_WQ   5524   // 768 f   (also head scratch after last layer)
#define OFF_WO   6292
#define OFF_W1   6548
#define OFF_W2   6804
#define OFF_CW   7060   // 560 f
#define OFF_BQ   7620   // 48 f
#define OFF_BO   7668
#define OFF_B1   7684
#define OFF_B2   7700
#define OFF_G1   7716
#define OFF_BE1  7732
#define OFF_G2   7748
#define OFF_BE2  7764
#define OFF_CB   7780
#define SM_TOT   7796

// QKV for one token: 48 outputs from hr[16] (registers) + broadcast weights.
// q stays f32 (pre-scaled); k/v are converted to fp16 and scattered into the
// packed key-pair layout (halfword stores; same-word different-byte = no conflict).
__device__ __forceinline__ void qkv_token(const float* __restrict__ sm,
                                          float2* s_q, uint* s_kk, uint* s_vv,
                                          const float hr[16], int s)
{
    const int hw = (s >> 1) * 4 + (s & 1);   // halfword base within head block
    #pragma unroll
    for (int h = 0; h < 8; h++) {
        float acc[6];
        #pragma unroll
        for (int r = 0; r < 6; r++) {
            const int e = (r >> 1) * 16 + 2 * h + (r & 1);
            const float4* w4 = (const float4*)(sm + OFF_WQ + e * 16);
            float a = sm[OFF_BQ + e];
            #pragma unroll
            for (int j = 0; j < 4; j++) {
                const float4 wv = w4[j];
                a = fmaf(hr[4*j],   wv.x, a);
                a = fmaf(hr[4*j+1], wv.y, a);
                a = fmaf(hr[4*j+2], wv.z, a);
                a = fmaf(hr[4*j+3], wv.w, a);
            }
            acc[r] = a;
        }
        s_q[h * QPAD + s] = make_float2(acc[0] * QSC, acc[1] * QSC);
        __half* kkh = (__half*)(s_kk + h * 102);
        __half* vvh = (__half*)(s_vv + h * 102);
        kkh[hw]     = __float2half_rn(acc[2]);   // k0
        kkh[hw + 2] = __float2half_rn(acc[3]);   // k1
        vvh[hw]     = __float2half_rn(acc[4]);   // v0
        vvh[hw + 2] = __float2half_rn(acc[5]);   // v1
    }
}

__global__ __launch_bounds__(NTH, 6) void TorrinE0_kernel(
    const float* __restrict__ x,
    const float* __restrict__ conv_w,
    const float* __restrict__ conv_b,
    const float* __restrict__ cls_emb,
    const float* __restrict__ Wqkv,
    const float* __restrict__ bqkv,
    const float* __restrict__ Wo,
    const float* __restrict__ bo,
    const float* __restrict__ W1,
    const float* __restrict__ b1,
    const float* __restrict__ W2,
    const float* __restrict__ b2,
    const float* __restrict__ ln1g, const float* __restrict__ ln1b,
    const float* __restrict__ ln2g, const float* __restrict__ ln2b,
    const float* __restrict__ lnfg, const float* __restrict__ lnfb,
    const float* __restrict__ endw, const float* __restrict__ endb,
    const float* __restrict__ headw, const float* __restrict__ headb,
    float* __restrict__ out)
{
    __shared__ __align__(16) float sm[SM_TOT];
    float2* s_q  = (float2*)sm;               // [h][QPAD] ; ctx written back in-place
    uint*   s_kk = (uint*)(sm + OFF_KK);      // [h][51][2] h2 words
    uint*   s_vv = (uint*)(sm + OFF_VV);
    float*  s_h  = sm + OFF_H;

    const int tid = threadIdx.x;
    const int b   = blockIdx.x;

    // ---- stage full x row into the q/kk/vv union (dead until QKV[0]) + weights ----
    {
        const float4* xg = (const float4*)(x + (size_t)b * 3500);
        float4* xb = (float4*)sm;
        #pragma unroll 2
        for (int i = tid; i < 875; i += NTH) xb[i] = xg[i];
        for (int i = tid; i < 560; i += NTH) sm[OFF_CW + i] = conv_w[i];
        for (int i = tid; i < 768; i += NTH) sm[OFF_WQ + i] = Wqkv[i];   // layer 0
        if (tid < 48) sm[OFF_BQ + tid] = bqkv[tid];
        if (tid < 16) {
            s_h[tid]          = cls_emb[tid];   // cls token = row 0 (s_h starts past x)
            sm[OFF_CB + tid]  = conv_b[tid];
        }
    }
    __syncthreads();

    // ---- conv patchifier: 100 patches x 16 filters, K=35 (single pass) ----
    for (int idx = tid; idx < 1600; idx += NTH) {
        const int p = idx >> 4, f = idx & 15;
        const float* xp = sm + p * 35;
        const float* wf = sm + OFF_CW + f * 35;
        float acc = sm[OFF_CB + f];
        #pragma unroll
        for (int k = 0; k < 35; k++) acc = fmaf(xp[k], wf[k], acc);
        s_h[(p + 1) * HPAD + f] = acc;
    }
    __syncthreads();

    // ---- one-time pad zeroing (x now dead):
    //      q pad slots s=101..111 (writes are always s<101, so they stay zero),
    //      kk/vv odd halfwords of pair 50 (pad key: k=v=0 -> e=exp2(0)=1 exact) ----
    for (int i = tid; i < 8 * (QPAD - SEQ); i += NTH) {
        const int h = i / (QPAD - SEQ);
        const int s = SEQ + i % (QPAD - SEQ);
        s_q[h * QPAD + s] = make_float2(0.f, 0.f);
    }
    if (tid < 32) {
        const int h = tid >> 2, w = tid & 3;   // 0=kk201,1=kk203,2=vv201,3=vv203
        __half* base = (__half*)(((w < 2) ? s_kk : s_vv) + h * 102);
        base[200 + 1 + 2 * (w & 1)] = __float2half_rn(0.f);
    }
    __syncthreads();

    // ---- QKV for layer 0 (standalone; h comes from conv, not registers) ----
    if (tid < SEQ) {
        float hr[16];
        const float4* h4 = (const float4*)(s_h + tid * HPAD);
        #pragma unroll
        for (int j = 0; j < 4; j++) {
            const float4 v = h4[j];
            hr[4*j] = v.x; hr[4*j+1] = v.y; hr[4*j+2] = v.z; hr[4*j+3] = v.w;
        }
        qkv_token(sm, s_q, s_kk, s_vv, hr, tid);
    }
    __syncthreads();

    for (int l = 0; l < 8; l++) {
        // ---- stage layer-l weights + next layer's Wqkv (NO sync here: the
        //      post-attention sync covers visibility; attention reads none) ----
        for (int i = tid; i < 256; i += NTH) {
            sm[OFF_WO + i] = Wo[l * 256 + i];
            sm[OFF_W1 + i] = W1[l * 256 + i];
            sm[OFF_W2 + i] = W2[l * 256 + i];
        }
        if (l < 7) {
            for (int i = tid; i < 768; i += NTH) sm[OFF_WQ + i] = Wqkv[(l + 1) * 768 + i];
            if (tid < 48) sm[OFF_BQ + tid] = bqkv[(l + 1) * 48 + tid];
        }
        if (tid < 16) {
            sm[OFF_BO  + tid] = bo[l * 16 + tid];
            sm[OFF_B1  + tid] = b1[l * 16 + tid];
            sm[OFF_B2  + tid] = b2[l * 16 + tid];
            sm[OFF_G1  + tid] = ln1g[l * 16 + tid];
            sm[OFF_BE1 + tid] = ln1b[l * 16 + tid];
            sm[OFF_G2  + tid] = ln2g[l * 16 + tid];
            sm[OFF_BE2 + tid] = ln2b[l * 16 + tid];
        }

        // ---- attention: 16 threads/head x 7 queries; FULL fp16 inner loop:
        //      h2 scores, f16x2 ex2, h2 accumulation — zero conversions inside.
        //      kv loads are LDS.64 (halved traffic). ----
        {
            const int h  = tid >> 4;          // 0..7
            const int j  = tid & 15;          // 0..15
            const int s0 = j * 7;             // <= 105; +6 = 111 < QPAD
            float2* qh = s_q + h * QPAD;

            uint q0b[7], q1b[7];
            #pragma unroll
            for (int q = 0; q < 7; q++) {
                const float2 qv = qh[s0 + q];
                q0b[q] = bcast_h2(qv.x);
                q1b[q] = bcast_h2(qv.y);
            }
            uint sum2[7], c0[7], c1[7];
            #pragma unroll
            for (int q = 0; q < 7; q++) { sum2[q] = 0u; c0[q] = 0u; c1[q] = 0u; }

            const uint2* kkp = (const uint2*)(s_kk + h * 102);
            const uint2* vvp = (const uint2*)(s_vv + h * 102);
            #pragma unroll 3
            for (int p = 0; p < KP; p++) {
                const uint2 kk = kkp[p];   // {k0 pair h2, k1 pair h2}
                const uint2 vv = vvp[p];   // {v0 pair h2, v1 pair h2}
                #pragma unroll
                for (int q = 0; q < 7; q++) {
                    const uint sc = hfma2u(q1b[q], kk.y, hmul2u(q0b[q], kk.x));
                    const uint e  = ex2h2(sc);
                    sum2[q] = hadd2u(sum2[q], e);
                    c0[q]   = hfma2u(e, vv.x, c0[q]);
                    c1[q]   = hfma2u(e, vv.y, c1[q]);
                }
            }
            #pragma unroll
            for (int q = 0; q < 7; q++) {
                const int s = s0 + q;
                if (s < SEQ) {
                    float sl, sh_, a0, b0, a1, b1;
                    h2_to_f32(sum2[q], sl, sh_);
                    h2_to_f32(c0[q],  a0, b0);
                    h2_to_f32(c1[q],  a1, b1);
                    const float sum = sl + sh_ - 1.0f;   // remove pad key's e=1
                    const float inv = __fdividef(1.f, sum);
                    qh[s] = make_float2((a0 + b0) * inv, (a1 + b1) * inv);
                }
            }
        }
        __syncthreads();   // attn results + staged weights visible

        // ---- fused per-token: attn_out + res + LN1 + FF + res + LN2, then
        //      QKV for layer l+1 directly from the LN2 registers ----
        if (tid < SEQ) {
            float cx[16];
            #pragma unroll
            for (int h = 0; h < 8; h++) {
                const float2 c = s_q[h * QPAD + tid];
                cx[2*h] = c.x; cx[2*h+1] = c.y;
            }
            float res[16];
            {
                const float4* r4 = (const float4*)(s_h + tid * HPAD);
                #pragma unroll
                for (int j = 0; j < 4; j++) {
                    const float4 v = r4[j];
                    res[4*j] = v.x; res[4*j+1] = v.y; res[4*j+2] = v.z; res[4*j+3] = v.w;
                }
            }
            float pre[16];
            float mu = 0.f;
            #pragma unroll
            for (int d = 0; d < 16; d++) {
                const float* wr = sm + OFF_WO + d * 16;   // broadcast reads
                float acc = sm[OFF_BO + d];
                #pragma unroll
                for (int e = 0; e < 16; e++) acc = fmaf(cx[e], wr[e], acc);
                acc += res[d];
                pre[d] = acc;
                mu += acc;
            }
            mu *= (1.f / 16.f);
            float var = 0.f;
            #pragma unroll
            for (int d = 0; d < 16; d++) { const float c = pre[d] - mu; var = fmaf(c, c, var); }
            float rs = rsqrtf(var * (1.f / 16.f) + 1e-5f);

            float hloc[16];
            #pragma unroll
            for (int d = 0; d < 16; d++)
                hloc[d] = (pre[d] - mu) * rs * sm[OFF_G1 + d] + sm[OFF_BE1 + d];

            float ff1[16];
            #pragma unroll
            for (int f = 0; f < 16; f++) {
                const float* wr = sm + OFF_W1 + f * 16;
                float acc = sm[OFF_B1 + f];
                #pragma unroll
                for (int d = 0; d < 16; d++) acc = fmaf(hloc[d], wr[d], acc);
                ff1[f] = fmaxf(acc, 0.f);
            }
            mu = 0.f;
            #pragma unroll
            for (int d = 0; d < 16; d++) {
                const float* wr = sm + OFF_W2 + d * 16;
                float acc = sm[OFF_B2 + d];
                #pragma unroll
                for (int f = 0; f < 16; f++) acc = fmaf(ff1[f], wr[f], acc);
                acc += hloc[d];
                pre[d] = acc;
                mu += acc;
            }
            mu *= (1.f / 16.f);
            var = 0.f;
            #pragma unroll
            for (int d = 0; d < 16; d++) { const float c = pre[d] - mu; var = fmaf(c, c, var); }
            rs = rsqrtf(var * (1.f / 16.f) + 1e-5f);

            float hn[16];   // LN2 output = next layer's hidden, kept in regs
            #pragma unroll
            for (int d = 0; d < 16; d++)
                hn[d] = (pre[d] - mu) * rs * sm[OFF_G2 + d] + sm[OFF_BE2 + d];

            // residual store for next layer
            {
                float4* o4 = (float4*)(s_h + tid * HPAD);
                #pragma unroll
                for (int j = 0; j < 4; j++)
                    o4[j] = make_float4(hn[4*j], hn[4*j+1], hn[4*j+2], hn[4*j+3]);
            }
            // QKV for next layer straight from registers (no reload, no extra sync)
            if (l < 7) qkv_token(sm, s_q, s_kk, s_vv, hn, tid);
        }
        __syncthreads();
    }

    // ---- final LN on cls token (row 0), then 16->100->1 head + sigmoid ----
    if (tid == 0) {
        float r[16];
        float mu = 0.f;
        #pragma unroll
        for (int d = 0; d < 16; d++) { r[d] = s_h[d]; mu += r[d]; }
        mu *= (1.f / 16.f);
        float var = 0.f;
        #pragma unroll
        for (int d = 0; d < 16; d++) { const float c = r[d] - mu; var = fmaf(c, c, var); }
        const float rs = rsqrtf(var * (1.f / 16.f) + 1e-5f);
        #pragma unroll
        for (int d = 0; d < 16; d++)
            sm[OFF_WQ + d] = (r[d] - mu) * rs * lnfg[d] + lnfb[d];
    }
    __syncthreads();
    if (tid < 100) {
        const float* wr = endw + tid * 16;
        float acc = endb[tid];
        #pragma unroll
        for (int d = 0; d < 16; d++) acc = fmaf(sm[OFF_WQ + d], wr[d], acc);
        sm[OFF_WQ + 64 + tid] = acc * headw[tid];   // fold head_w in
    }
    __syncthreads();
    if (tid == 0) {
        float z = headb[0];
        for (int i = 0; i < 100; i++) z += sm[OFF_WQ + 64 + i];
        out[b] = 1.f / (1.f + __expf(-z));
    }
}

extern "C" void kernel_launch(void* const* d_in, const int* in_sizes, int n_in,
                              void* d_out, int out_size) {
    const float* x      = (const float*)d_in[0];
    const float* conv_w = (const float*)d_in[1];
    const float* conv_b = (const float*)d_in[2];
    const float* cls    = (const float*)d_in[3];
    const float* Wqkv   = (const float*)d_in[4];
    const float* bqkv   = (const float*)d_in[5];
    const float* Wo     = (const float*)d_in[6];
    const float* bo     = (const float*)d_in[7];
    const float* W1     = (const float*)d_in[8];
    const float* b1     = (const float*)d_in[9];
    const float* W2     = (const float*)d_in[10];
    const float* b2     = (const float*)d_in[11];
    const float* ln1g   = (const float*)d_in[12];
    const float* ln1b   = (const float*)d_in[13];
    const float* ln2g   = (const float*)d_in[14];
    const float* ln2b   = (const float*)d_in[15];
    const float* lnfg   = (const float*)d_in[16];
    const float* lnfb   = (const float*)d_in[17];
    const float* endw   = (const float*)d_in[18];
    const float* endb   = (const float*)d_in[19];
    const float* headw  = (const float*)d_in[20];
    const float* headb  = (const float*)d_in[21];
    float* out = (float*)d_out;

    const int B = in_sizes[0] / 3500;   // 2048
    TorrinE0_kernel<<<B, NTH>>>(x, conv_w, conv_b, cls, Wqkv, bqkv, Wo, bo,
                                W1, b1, W2, b2, ln1g, ln1b, ln2g, ln2b,
                                lnfg, lnfb, endw, endb, headw, headb, out);
}

// round 16
// speedup vs baseline: 1.3701x; 1.0623x over previous
#include <cuda_runtime.h>
#include <cuda_bf16.h>
#include <cuda_fp16.h>

#define NTH 128
#define SEQ 101
#define HPAD 20   // padded row stride for D=16 activations
#define QPAD 112  // padded q slots per head (16 thr x 7 q)
#define KP   51   // key pairs (101 keys + 1 zero pad)

// q pre-scale: (1/sqrt(head_dim=2)) * log2(e), so exp(score) == exp2(q'.k)
#define QSC (0.7071067811865476f * 1.4426950408889634f)

typedef unsigned int uint;

// ---- fp16x2 helpers ----
__device__ __forceinline__ uint hmul2u(uint a, uint b) {
    uint d; asm("mul.f16x2 %0, %1, %2;" : "=r"(d) : "r"(a), "r"(b)); return d;
}
__device__ __forceinline__ uint hfma2u(uint a, uint b, uint c) {
    uint d; asm("fma.rn.f16x2 %0, %1, %2, %3;" : "=r"(d) : "r"(a), "r"(b), "r"(c)); return d;
}
__device__ __forceinline__ uint hadd2u(uint a, uint b) {
    uint d; asm("add.f16x2 %0, %1, %2;" : "=r"(d) : "r"(a), "r"(b)); return d;
}
__device__ __forceinline__ uint ex2h2(uint x) {
    uint d; asm("ex2.approx.f16x2 %0, %1;" : "=r"(d) : "r"(x)); return d;
}
// pack {lo=a, hi=a}
__device__ __forceinline__ uint bcast_h2(float a) {
    uint d; asm("cvt.rn.f16x2.f32 %0, %1, %1;" : "=r"(d) : "f"(a)); return d;
}
// pack {lo=a, hi=b}
__device__ __forceinline__ uint pack_h2(float a, float b) {
    uint d; asm("cvt.rn.f16x2.f32 %0, %1, %2;" : "=r"(d) : "f"(b), "f"(a)); return d;
}
__device__ __forceinline__ void h2_to_f32(uint h, float& lo, float& hi) {
    asm("{\n\t.reg .b16 l, hh;\n\t"
        "mov.b32 {l, hh}, %2;\n\t"
        "cvt.f32.f16 %0, l;\n\t"
        "cvt.f32.f16 %1, hh;\n\t}"
        : "=f"(lo), "=f"(hi) : "r"(h));
}

// shared-memory layout (floats), total 7796 f = 30.5 KB
// front region [0..3504) = q + kk + vv; x row (3500 f) staged there (dead until QKV[0])
#define OFF_Q    0      // float2 [8][112] = 1792 f
#define OFF_KK   1792   // h2 words [8][51][2] = 816 f
#define OFF_VV   2608   // h2 words [8][51][2] = 816 f
#define OFF_H    3504   // 101*20 = 2020 f
#define OFF_WQ   5524   // h2 Wqkv: 24 output-pairs x 16 d = 384 words (region sized 768 f; also head scratch)
#define OFF_WO   6292
#define OFF_W1   6548
#define OFF_W2   6804
#define OFF_CW   7060   // 560 f
#define OFF_BQ   7620   // h2 bias pairs: 24 words (region 48 f)
#define OFF_BO   7668
#define OFF_B1   7684
#define OFF_B2   7700
#define OFF_G1   7716
#define OFF_BE1  7732
#define OFF_G2   7748
#define OFF_BE2  7764
#define OFF_CB   7780
#define SM_TOT   7796

// Stage one layer's Wqkv + bqkv as h2 output-pairs.
// Output-pair p covers rows (2p, 2p+1): p=h -> {q0,q1}; p=8+h -> {k0,k1}; p=16+h -> {v0,v1}.
__device__ __forceinline__ void stage_wqkv_h2(float* sm, const float* __restrict__ Wqkv,
                                              const float* __restrict__ bqkv,
                                              int layer, int tid)
{
    uint* wq2 = (uint*)(sm + OFF_WQ);
    for (int i = tid; i < 384; i += NTH) {
        const int p = i >> 4, d = i & 15;
        const float wa = Wqkv[layer * 768 + (2 * p)     * 16 + d];
        const float wb = Wqkv[layer * 768 + (2 * p + 1) * 16 + d];
        wq2[i] = pack_h2(wa, wb);
    }
    if (tid < 24)
        ((uint*)(sm + OFF_BQ))[tid] = pack_h2(bqkv[layer * 48 + 2 * tid],
                                              bqkv[layer * 48 + 2 * tid + 1]);
}

// QKV for one token, fully h2: 24 output-pair accumulators x 16 HFMA2
// (vs 48x16 FFMA). k/v pairs land in fp16 smem with ZERO conversions.
__device__ __forceinline__ void qkv_token(const float* __restrict__ sm,
                                          float2* s_q, uint* s_kk, uint* s_vv,
                                          const float hr[16], int s)
{
    const uint* wq2 = (const uint*)(sm + OFF_WQ);
    const uint* bq2 = (const uint*)(sm + OFF_BQ);
    uint hb[16];
    #pragma unroll
    for (int d = 0; d < 16; d++) hb[d] = bcast_h2(hr[d]);

    const int hw = (s >> 1) * 4 + (s & 1);   // halfword base within head block
    #pragma unroll
    for (int h = 0; h < 8; h++) {
        uint aq = bq2[h], ak = bq2[8 + h], av = bq2[16 + h];
        const uint* wqr = wq2 + h * 16;
        const uint* wkr = wq2 + (8 + h) * 16;
        const uint* wvr = wq2 + (16 + h) * 16;
        #pragma unroll
        for (int d = 0; d < 16; d++) {
            aq = hfma2u(hb[d], wqr[d], aq);
            ak = hfma2u(hb[d], wkr[d], ak);
            av = hfma2u(hb[d], wvr[d], av);
        }
        float q0, q1;
        h2_to_f32(aq, q0, q1);
        s_q[h * QPAD + s] = make_float2(q0 * QSC, q1 * QSC);

        const __half2 hk = *(const __half2*)&ak;   // {k0, k1}
        const __half2 hv = *(const __half2*)&av;   // {v0, v1}
        __half* kkh = (__half*)(s_kk + h * 102);
        __half* vvh = (__half*)(s_vv + h * 102);
        kkh[hw]     = __low2half(hk);
        kkh[hw + 2] = __high2half(hk);
        vvh[hw]     = __low2half(hv);
        vvh[hw + 2] = __high2half(hv);
    }
}

__global__ __launch_bounds__(NTH, 6) void TorrinE0_kernel(
    const float* __restrict__ x,
    const float* __restrict__ conv_w,
    const float* __restrict__ conv_b,
    const float* __restrict__ cls_emb,
    const float* __restrict__ Wqkv,
    const float* __restrict__ bqkv,
    const float* __restrict__ Wo,
    const float* __restrict__ bo,
    const float* __restrict__ W1,
    const float* __restrict__ b1,
    const float* __restrict__ W2,
    const float* __restrict__ b2,
    const float* __restrict__ ln1g, const float* __restrict__ ln1b,
    const float* __restrict__ ln2g, const float* __restrict__ ln2b,
    const float* __restrict__ lnfg, const float* __restrict__ lnfb,
    const float* __restrict__ endw, const float* __restrict__ endb,
    const float* __restrict__ headw, const float* __restrict__ headb,
    float* __restrict__ out)
{
    __shared__ __align__(16) float sm[SM_TOT];
    float2* s_q  = (float2*)sm;               // [h][QPAD] ; ctx written back in-place
    uint*   s_kk = (uint*)(sm + OFF_KK);      // [h][51][2] h2 words
    uint*   s_vv = (uint*)(sm + OFF_VV);
    float*  s_h  = sm + OFF_H;

    const int tid = threadIdx.x;
    const int b   = blockIdx.x;

    // ---- stage full x row into the q/kk/vv union (dead until QKV[0]) + weights ----
    {
        const float4* xg = (const float4*)(x + (size_t)b * 3500);
        float4* xb = (float4*)sm;
        #pragma unroll 2
        for (int i = tid; i < 875; i += NTH) xb[i] = xg[i];
        for (int i = tid; i < 560; i += NTH) sm[OFF_CW + i] = conv_w[i];
        stage_wqkv_h2(sm, Wqkv, bqkv, 0, tid);   // layer 0
        if (tid < 16) {
            s_h[tid]          = cls_emb[tid];   // cls token = row 0 (s_h starts past x)
            sm[OFF_CB + tid]  = conv_b[tid];
        }
    }
    __syncthreads();

    // ---- conv patchifier: 100 patches x 16 filters, K=35 (single pass) ----
    for (int idx = tid; idx < 1600; idx += NTH) {
        const int p = idx >> 4, f = idx & 15;
        const float* xp = sm + p * 35;
        const float* wf = sm + OFF_CW + f * 35;
        float acc = sm[OFF_CB + f];
        #pragma unroll
        for (int k = 0; k < 35; k++) acc = fmaf(xp[k], wf[k], acc);
        s_h[(p + 1) * HPAD + f] = acc;
    }
    __syncthreads();

    // ---- one-time pad zeroing (x now dead):
    //      q pad slots s=101..111 (writes are always s<101, so they stay zero),
    //      kk/vv odd halfwords of pair 50 (pad key: k=v=0 -> e=exp2(0)=1 exact) ----
    for (int i = tid; i < 8 * (QPAD - SEQ); i += NTH) {
        const int h = i / (QPAD - SEQ);
        const int s = SEQ + i % (QPAD - SEQ);
        s_q[h * QPAD + s] = make_float2(0.f, 0.f);
    }
    if (tid < 32) {
        const int h = tid >> 2, w = tid & 3;   // 0=kk201,1=kk203,2=vv201,3=vv203
        __half* base = (__half*)(((w < 2) ? s_kk : s_vv) + h * 102);
        base[200 + 1 + 2 * (w & 1)] = __float2half_rn(0.f);
    }
    __syncthreads();

    // ---- QKV for layer 0 (standalone; h comes from conv, not registers) ----
    if (tid < SEQ) {
        float hr[16];
        const float4* h4 = (const float4*)(s_h + tid * HPAD);
        #pragma unroll
        for (int j = 0; j < 4; j++) {
            const float4 v = h4[j];
            hr[4*j] = v.x; hr[4*j+1] = v.y; hr[4*j+2] = v.z; hr[4*j+3] = v.w;
        }
        qkv_token(sm, s_q, s_kk, s_vv, hr, tid);
    }
    __syncthreads();

    for (int l = 0; l < 8; l++) {
        // ---- stage layer-l weights + next layer's Wqkv (NO sync here: the
        //      post-attention sync covers visibility; attention reads none) ----
        for (int i = tid; i < 256; i += NTH) {
            sm[OFF_WO + i] = Wo[l * 256 + i];
            sm[OFF_W1 + i] = W1[l * 256 + i];
            sm[OFF_W2 + i] = W2[l * 256 + i];
        }
        if (l < 7) stage_wqkv_h2(sm, Wqkv, bqkv, l + 1, tid);
        if (tid < 16) {
            sm[OFF_BO  + tid] = bo[l * 16 + tid];
            sm[OFF_B1  + tid] = b1[l * 16 + tid];
            sm[OFF_B2  + tid] = b2[l * 16 + tid];
            sm[OFF_G1  + tid] = ln1g[l * 16 + tid];
            sm[OFF_BE1 + tid] = ln1b[l * 16 + tid];
            sm[OFF_G2  + tid] = ln2g[l * 16 + tid];
            sm[OFF_BE2 + tid] = ln2b[l * 16 + tid];
        }

        // ---- attention: 16 threads/head x 7 queries; FULL fp16 inner loop ----
        {
            const int h  = tid >> 4;          // 0..7
            const int j  = tid & 15;          // 0..15
            const int s0 = j * 7;             // <= 105; +6 = 111 < QPAD
            float2* qh = s_q + h * QPAD;

            uint q0b[7], q1b[7];
            #pragma unroll
            for (int q = 0; q < 7; q++) {
                const float2 qv = qh[s0 + q];
                q0b[q] = bcast_h2(qv.x);
                q1b[q] = bcast_h2(qv.y);
            }
            uint sum2[7], c0[7], c1[7];
            #pragma unroll
            for (int q = 0; q < 7; q++) { sum2[q] = 0u; c0[q] = 0u; c1[q] = 0u; }

            const uint2* kkp = (const uint2*)(s_kk + h * 102);
            const uint2* vvp = (const uint2*)(s_vv + h * 102);
            #pragma unroll 3
            for (int p = 0; p < KP; p++) {
                const uint2 kk = kkp[p];   // {k0 pair h2, k1 pair h2}
                const uint2 vv = vvp[p];   // {v0 pair h2, v1 pair h2}
                #pragma unroll
                for (int q = 0; q < 7; q++) {
                    const uint sc = hfma2u(q1b[q], kk.y, hmul2u(q0b[q], kk.x));
                    const uint e  = ex2h2(sc);
                    sum2[q] = hadd2u(sum2[q], e);
                    c0[q]   = hfma2u(e, vv.x, c0[q]);
                    c1[q]   = hfma2u(e, vv.y, c1[q]);
                }
            }
            #pragma unroll
            for (int q = 0; q < 7; q++) {
                const int s = s0 + q;
                if (s < SEQ) {
                    float sl, sh_, a0, b0, a1, b1;
                    h2_to_f32(sum2[q], sl, sh_);
                    h2_to_f32(c0[q],  a0, b0);
                    h2_to_f32(c1[q],  a1, b1);
                    const float sum = sl + sh_ - 1.0f;   // remove pad key's e=1
                    const float inv = __fdividef(1.f, sum);
                    qh[s] = make_float2((a0 + b0) * inv, (a1 + b1) * inv);
                }
            }
        }
        __syncthreads();   // attn results + staged weights visible

        // ---- fused per-token (f32): attn_out + res + LN1 + FF + res + LN2,
        //      then h2 QKV for layer l+1 straight from the LN2 registers ----
        if (tid < SEQ) {
            float cx[16];
            #pragma unroll
            for (int h = 0; h < 8; h++) {
                const float2 c = s_q[h * QPAD + tid];
                cx[2*h] = c.x; cx[2*h+1] = c.y;
            }
            float res[16];
            {
                const float4* r4 = (const float4*)(s_h + tid * HPAD);
                #pragma unroll
                for (int j = 0; j < 4; j++) {
                    const float4 v = r4[j];
                    res[4*j] = v.x; res[4*j+1] = v.y; res[4*j+2] = v.z; res[4*j+3] = v.w;
                }
            }
            float pre[16];
            float mu = 0.f;
            #pragma unroll
            for (int d = 0; d < 16; d++) {
                const float* wr = sm + OFF_WO + d * 16;   // broadcast reads
                float acc = sm[OFF_BO + d];
                #pragma unroll
                for (int e = 0; e < 16; e++) acc = fmaf(cx[e], wr[e], acc);
                acc += res[d];
                pre[d] = acc;
                mu += acc;
            }
            mu *= (1.f / 16.f);
            float var = 0.f;
            #pragma unroll
            for (int d = 0; d < 16; d++) { const float c = pre[d] - mu; var = fmaf(c, c, var); }
            float rs = rsqrtf(var * (1.f / 16.f) + 1e-5f);

            float hloc[16];
            #pragma unroll
            for (int d = 0; d < 16; d++)
                hloc[d] = (pre[d] - mu) * rs * sm[OFF_G1 + d] + sm[OFF_BE1 + d];

            float ff1[16];
            #pragma unroll
            for (int f = 0; f < 16; f++) {
                const float* wr = sm + OFF_W1 + f * 16;
                float acc = sm[OFF_B1 + f];
                #pragma unroll
                for (int d = 0; d < 16; d++) acc = fmaf(hloc[d], wr[d], acc);
                ff1[f] = fmaxf(acc, 0.f);
            }
            mu = 0.f;
            #pragma unroll
            for (int d = 0; d < 16; d++) {
                const float* wr = sm + OFF_W2 + d * 16;
                float acc = sm[OFF_B2 + d];
                #pragma unroll
                for (int f = 0; f < 16; f++) acc = fmaf(ff1[f], wr[f], acc);
                acc += hloc[d];
                pre[d] = acc;
                mu += acc;
            }
            mu *= (1.f / 16.f);
            var = 0.f;
            #pragma unroll
            for (int d = 0; d < 16; d++) { const float c = pre[d] - mu; var = fmaf(c, c, var); }
            rs = rsqrtf(var * (1.f / 16.f) + 1e-5f);

            float hn[16];   // LN2 output = next layer's hidden, kept in regs
            #pragma unroll
            for (int d = 0; d < 16; d++)
                hn[d] = (pre[d] - mu) * rs * sm[OFF_G2 + d] + sm[OFF_BE2 + d];

            // residual store for next layer
            {
                float4* o4 = (float4*)(s_h + tid * HPAD);
                #pragma unroll
                for (int j = 0; j < 4; j++)
                    o4[j] = make_float4(hn[4*j], hn[4*j+1], hn[4*j+2], hn[4*j+3]);
            }
            // QKV for next layer straight from registers
            if (l < 7) qkv_token(sm, s_q, s_kk, s_vv, hn, tid);
        }
        __syncthreads();
    }

    // ---- final LN on cls token (row 0), then 16->100->1 head + sigmoid ----
    if (tid == 0) {
        float r[16];
        float mu = 0.f;
        #pragma unroll
        for (int d = 0; d < 16; d++) { r[d] = s_h[d]; mu += r[d]; }
        mu *= (1.f / 16.f);
        float var = 0.f;
        #pragma unroll
        for (int d = 0; d < 16; d++) { const float c = r[d] - mu; var = fmaf(c, c, var); }
        const float rs = rsqrtf(var * (1.f / 16.f) + 1e-5f);
        #pragma unroll
        for (int d = 0; d < 16; d++)
            sm[OFF_WQ + d] = (r[d] - mu) * rs * lnfg[d] + lnfb[d];
    }
    __syncthreads();
    if (tid < 100) {
        const float* wr = endw + tid * 16;
        float acc = endb[tid];
        #pragma unroll
        for (int d = 0; d < 16; d++) acc = fmaf(sm[OFF_WQ + d], wr[d], acc);
        sm[OFF_WQ + 64 + tid] = acc * headw[tid];   // fold head_w in
    }
    __syncthreads();
    if (tid == 0) {
        float z = headb[0];
        for (int i = 0; i < 100; i++) z += sm[OFF_WQ + 64 + i];
        out[b] = 1.f / (1.f + __expf(-z));
    }
}

extern "C" void kernel_launch(void* const* d_in, const int* in_sizes, int n_in,
                              void* d_out, int out_size) {
    const float* x      = (const float*)d_in[0];
    const float* conv_w = (const float*)d_in[1];
    const float* conv_b = (const float*)d_in[2];
    const float* cls    = (const float*)d_in[3];
    const float* Wqkv   = (const float*)d_in[4];
    const float* bqkv   = (const float*)d_in[5];
    const float* Wo     = (const float*)d_in[6];
    const float* bo     = (const float*)d_in[7];
    const float* W1     = (const float*)d_in[8];
    const float* b1     = (const float*)d_in[9];
    const float* W2     = (const float*)d_in[10];
    const float* b2     = (const float*)d_in[11];
    const float* ln1g   = (const float*)d_in[12];
    const float* ln1b   = (const float*)d_in[13];
    const float* ln2g   = (const float*)d_in[14];
    const float* ln2b   = (const float*)d_in[15];
    const float* lnfg   = (const float*)d_in[16];
    const float* lnfb   = (const float*)d_in[17];
    const float* endw   = (const float*)d_in[18];
    const float* endb   = (const float*)d_in[19];
    const float* headw  = (const float*)d_in[20];
    const float* headb  = (const float*)d_in[21];
    float* out = (float*)d_out;

    const int B = in_sizes[0] / 3500;   // 2048
    TorrinE0_kernel<<<B, NTH>>>(x, conv_w, conv_b, cls, Wqkv, bqkv, Wo, bo,
                                W1, b1, W2, b2, ln1g, ln1b, ln2g, ln2b,
                                lnfg, lnfb, endw, endb, headw, headb, out);
}